// round 13
// baseline (speedup 1.0000x reference)
#include <cuda_runtime.h>
#include <cuda_bf16.h>
#include <cuda_fp16.h>
#include <math.h>
#include <stdint.h>

// Problem constants
#define NB   8
#define SS   512
#define DD   4096
#define HH   8
#define HD_  512
#define MT   (NB*SS)            // 4096
#define BSTR ((long long)SS*SS) // 262144
#define NELT (MT*DD)            // 16,777,216

// ---------------- scratch (device globals; allocation-guard safe) -----------
__device__ float g_v[NELT];             // V projection (fp32)
__device__ float g_s[NELT];             // scores (fp32)
__device__ __nv_bfloat16 g_qa_h[NELT], g_qa_l[NELT];
__device__ __nv_bfloat16 g_ka_h[NELT], g_ka_l[NELT];
__device__ __nv_bfloat16 g_wq_h[NELT], g_wq_l[NELT];
__device__ __nv_bfloat16 g_wk_h[NELT], g_wk_l[NELT];
__device__ __nv_bfloat16 g_q_h [NELT], g_q_l [NELT];
__device__ __nv_bfloat16 g_k_h [NELT], g_k_l [NELT];
__device__ __half g_va[NELT];
__device__ __half g_wv[NELT];
__device__ __half g_wo[NELT];
__device__ __half g_y_h[NELT];          // Y2 fp16 (hi only)

// ---------------- stream/event resources (static init, pre-checkpoint) ------
struct HxStreams {
    cudaStream_t s1;
    cudaEvent_t ef, eWq, ek, ev, ewo, esc, eoB;
    HxStreams() {
        cudaStreamCreateWithFlags(&s1, cudaStreamNonBlocking);
        cudaEventCreateWithFlags(&ef,  cudaEventDisableTiming);
        cudaEventCreateWithFlags(&eWq, cudaEventDisableTiming);
        cudaEventCreateWithFlags(&ek,  cudaEventDisableTiming);
        cudaEventCreateWithFlags(&ev,  cudaEventDisableTiming);
        cudaEventCreateWithFlags(&ewo, cudaEventDisableTiming);
        cudaEventCreateWithFlags(&esc, cudaEventDisableTiming);
        cudaEventCreateWithFlags(&eoB, cudaEventDisableTiming);
    }
};
static HxStreams g_sx;

// ---------------- PTX helpers (compute_103-baseline legal) ------------------
__device__ __forceinline__ uint32_t smem_u32(const void* p) {
    uint32_t a;
    asm("{ .reg .u64 t; cvta.to.shared.u64 t, %1; cvt.u32.u64 %0, t; }"
        : "=r"(a) : "l"(p));
    return a;
}
__device__ __forceinline__ void cp16(uint32_t s, const void* g) {
    asm volatile("cp.async.cg.shared.global [%0], [%1], 16;" :: "r"(s), "l"(g));
}
__device__ __forceinline__ void cp_commit() {
    asm volatile("cp.async.commit_group;");
}
template <int N> __device__ __forceinline__ void cp_wait() {
    asm volatile("cp.async.wait_group %0;" :: "n"(N));
}
__device__ __forceinline__ void ldsm4(uint32_t& r0, uint32_t& r1,
                                      uint32_t& r2, uint32_t& r3, uint32_t a) {
    asm volatile("ldmatrix.sync.aligned.m8n8.x4.shared.b16 {%0,%1,%2,%3}, [%4];"
                 : "=r"(r0), "=r"(r1), "=r"(r2), "=r"(r3) : "r"(a));
}
template<bool FP16>
__device__ __forceinline__ void mma16816(float* d, const uint32_t* a,
                                         uint32_t b0, uint32_t b1) {
    if constexpr (FP16) {
        asm("mma.sync.aligned.m16n8k16.row.col.f32.f16.f16.f32 "
            "{%0,%1,%2,%3}, {%4,%5,%6,%7}, {%8,%9}, {%0,%1,%2,%3};"
            : "+f"(d[0]), "+f"(d[1]), "+f"(d[2]), "+f"(d[3])
            : "r"(a[0]), "r"(a[1]), "r"(a[2]), "r"(a[3]), "r"(b0), "r"(b1));
    } else {
        asm("mma.sync.aligned.m16n8k16.row.col.f32.bf16.bf16.f32 "
            "{%0,%1,%2,%3}, {%4,%5,%6,%7}, {%8,%9}, {%0,%1,%2,%3};"
            : "+f"(d[0]), "+f"(d[1]), "+f"(d[2]), "+f"(d[3])
            : "r"(a[0]), "r"(a[1]), "r"(a[2]), "r"(a[3]), "r"(b0), "r"(b1));
    }
}

// ---------------- tile constants --------------------------------------------
#define BM 128
#define BN 128
#define BK 64
// SW128 layout: 128B per row (64 x b16). row r, 16B chunk c:
// byte = r*128 + ((c*16) ^ ((r&7)<<4)).

// ---------------------------------------------------------------------------
// HMMA NT GEMM: C = scale * A B^T (+ bias).  Passes: AhBh [+ AhBl][+ AlBh].
// ---------------------------------------------------------------------------
template<bool HAS_AL, bool HAS_BL, bool FP16, int MINB>
__global__ void __launch_bounds__(256, MINB)
gemm_tc(const uint16_t* __restrict__ Ah, const uint16_t* __restrict__ Al,
        const uint16_t* __restrict__ Bh, const uint16_t* __restrict__ Bl,
        float* __restrict__ C, __nv_bfloat16* __restrict__ Ch,
        __nv_bfloat16* __restrict__ Cl, const float* __restrict__ bias,
        int Nn, int Kk, long long sA, long long sB, long long sC, float scale)
{
    constexpr uint32_t SZ_A = 128 * 128;    // 16KB
    constexpr uint32_t SZ_B = 128 * 128;    // 16KB
    constexpr uint32_t OFF_BH = SZ_A * (1 + (HAS_AL ? 1 : 0));
    constexpr uint32_t STG_SZ = SZ_A * (1 + (HAS_AL ? 1 : 0))
                              + SZ_B * (1 + (HAS_BL ? 1 : 0));
    constexpr int STAGES = 3;

    extern __shared__ __align__(1024) char smem[];
    const uint32_t sb = smem_u32(smem);
    const int tid = threadIdx.x;
    const int bz = blockIdx.z;
    Ah += (long long)bz * sA;  if (HAS_AL) Al += (long long)bz * sA;
    Bh += (long long)bz * sB;  if (HAS_BL) Bl += (long long)bz * sB;

    const int m0 = blockIdx.y * BM;
    const int n0 = blockIdx.x * BN;
    const int nst = Kk / BK;

    auto load_stage = [&](int s, int buf) {
        const uint32_t stg = sb + (uint32_t)buf * STG_SZ;
        const int kk = s * BK;
        #pragma unroll
        for (int it = 0; it < 4; it++) {
            int id = tid + it * 256;
            int r = id >> 3, c = id & 7;
            long long go = (long long)(m0 + r) * Kk + kk + c * 8;
            uint32_t so = (uint32_t)(r * 128 + ((c * 16) ^ ((r & 7) << 4)));
            cp16(stg + so, Ah + go);
            if (HAS_AL) cp16(stg + SZ_A + so, Al + go);
        }
        #pragma unroll
        for (int it = 0; it < 4; it++) {
            int id = tid + it * 256;
            int r = id >> 3, c = id & 7;
            long long go = (long long)(n0 + r) * Kk + kk + c * 8;
            uint32_t so = (uint32_t)(r * 128 + ((c * 16) ^ ((r & 7) << 4)));
            cp16(stg + OFF_BH + so, Bh + go);
            if (HAS_BL) cp16(stg + OFF_BH + SZ_B + so, Bl + go);
        }
    };

    // 2x4 warps, warp tile 64x32
    const int wid = tid >> 5, lane = tid & 31;
    const int warp_m = wid & 1;
    const int warp_n = wid >> 1;
    const int arow0 = warp_m * 64 + (lane & 15);
    const int brow0 = warp_n * 32 + (lane & 15);
    const uint32_t halfsel = (uint32_t)((lane >> 4) * 16);

    float acc[4][4][4];
    #pragma unroll
    for (int i = 0; i < 4; i++)
        #pragma unroll
        for (int j = 0; j < 4; j++)
            #pragma unroll
            for (int k = 0; k < 4; k++) acc[i][j][k] = 0.f;

    #pragma unroll
    for (int s = 0; s < STAGES - 1; s++) {
        if (s < nst) { load_stage(s, s); cp_commit(); }
    }

    for (int c = 0; c < nst; c++) {
        cp_wait<STAGES - 2>();
        __syncthreads();
        if (c + STAGES - 1 < nst) {
            load_stage(c + STAGES - 1, (c + STAGES - 1) % STAGES);
            cp_commit();
        }
        const uint32_t stg = sb + (uint32_t)(c % STAGES) * STG_SZ;

        #pragma unroll
        for (int ks = 0; ks < 4; ks++) {
            const uint32_t ko = (uint32_t)(ks * 32);
            uint32_t ah[4][4], al[4][4];
            #pragma unroll
            for (int mt = 0; mt < 4; mt++) {
                int row = arow0 + mt * 16;
                uint32_t ad = stg + (uint32_t)row * 128
                            + ((ko + halfsel) ^ (uint32_t)((row & 7) << 4));
                ldsm4(ah[mt][0], ah[mt][1], ah[mt][2], ah[mt][3], ad);
                if (HAS_AL)
                    ldsm4(al[mt][0], al[mt][1], al[mt][2], al[mt][3], ad + SZ_A);
            }
            #pragma unroll
            for (int g = 0; g < 2; g++) {
                int row = brow0 + g * 16;
                uint32_t bd = stg + OFF_BH + (uint32_t)row * 128
                            + ((ko + halfsel) ^ (uint32_t)((row & 7) << 4));
                uint32_t bh[4], bl[4];
                ldsm4(bh[0], bh[1], bh[2], bh[3], bd);
                if (HAS_BL) ldsm4(bl[0], bl[1], bl[2], bl[3], bd + SZ_B);
                #pragma unroll
                for (int half = 0; half < 2; half++) {
                    const int nt = g * 2 + half;
                    const uint32_t b0h = bh[half], b1h = bh[half + 2];
                    #pragma unroll
                    for (int mt = 0; mt < 4; mt++) {
                        mma16816<FP16>(acc[mt][nt], ah[mt], b0h, b1h);
                        if (HAS_BL)
                            mma16816<FP16>(acc[mt][nt], ah[mt], bl[half], bl[half + 2]);
                        if (HAS_AL)
                            mma16816<FP16>(acc[mt][nt], al[mt], b0h, b1h);
                    }
                }
            }
        }
    }

    // ---- epilogue --------------------------------------------------------
    const int r0 = lane >> 2;
    const int c0 = (lane & 3) * 2;
    float* Cp = C ? (C + (long long)bz * sC) : nullptr;
    __nv_bfloat16* Chp = Ch ? (Ch + (long long)bz * sC) : nullptr;
    __nv_bfloat16* Clp = Cl ? (Cl + (long long)bz * sC) : nullptr;

    #pragma unroll
    for (int mt = 0; mt < 4; mt++) {
        #pragma unroll
        for (int nt = 0; nt < 4; nt++) {
            const int gc = n0 + warp_n * 32 + nt * 8 + c0;
            float b0 = 0.f, b1 = 0.f;
            if (bias) { b0 = __ldg(&bias[gc]); b1 = __ldg(&bias[gc + 1]); }
            #pragma unroll
            for (int hh = 0; hh < 2; hh++) {
                const int gr = m0 + warp_m * 64 + mt * 16 + r0 + hh * 8;
                float v0 = acc[mt][nt][hh * 2 + 0] * scale + b0;
                float v1 = acc[mt][nt][hh * 2 + 1] * scale + b1;
                if (Cp) {
                    float2 o = make_float2(v0, v1);
                    *(float2*)(Cp + (long long)gr * Nn + gc) = o;
                }
                if (Chp) {
                    __nv_bfloat16 h0 = __float2bfloat16(v0);
                    __nv_bfloat16 h1 = __float2bfloat16(v1);
                    __nv_bfloat16 l0 = __float2bfloat16(v0 - __bfloat162float(h0));
                    __nv_bfloat16 l1 = __float2bfloat16(v1 - __bfloat162float(h1));
                    __nv_bfloat162 hp(h0, h1), lp(l0, l1);
                    *(uint32_t*)(Chp + (long long)gr * Nn + gc) = *(uint32_t*)&hp;
                    *(uint32_t*)(Clp + (long long)gr * Nn + gc) = *(uint32_t*)&lp;
                }
            }
        }
    }
}

// ---------------------------------------------------------------------------
// fp32 -> bf16 hi/lo split
__global__ void __launch_bounds__(256)
split2_bf16(const float4* __restrict__ in, uint2* __restrict__ hi,
            uint2* __restrict__ lo, int n4)
{
    int i = blockIdx.x * blockDim.x + threadIdx.x;
    if (i >= n4) return;
    float4 a = in[i];
    __nv_bfloat16 h0 = __float2bfloat16(a.x), h1 = __float2bfloat16(a.y);
    __nv_bfloat16 h2 = __float2bfloat16(a.z), h3 = __float2bfloat16(a.w);
    __nv_bfloat16 l0 = __float2bfloat16(a.x - __bfloat162float(h0));
    __nv_bfloat16 l1 = __float2bfloat16(a.y - __bfloat162float(h1));
    __nv_bfloat16 l2 = __float2bfloat16(a.z - __bfloat162float(h2));
    __nv_bfloat16 l3 = __float2bfloat16(a.w - __bfloat162float(h3));
    __nv_bfloat162 hA(h0, h1), hB(h2, h3), lA(l0, l1), lB(l2, l3);
    hi[i] = make_uint2(*(uint32_t*)&hA, *(uint32_t*)&hB);
    lo[i] = make_uint2(*(uint32_t*)&lA, *(uint32_t*)&lB);
}

// fp32 -> fp16
__global__ void __launch_bounds__(256)
split1_f16(const float4* __restrict__ in, uint2* __restrict__ hi, int n4)
{
    int i = blockIdx.x * blockDim.x + threadIdx.x;
    if (i >= n4) return;
    float4 a = in[i];
    __half2 hA(__float2half_rn(a.x), __float2half_rn(a.y));
    __half2 hB(__float2half_rn(a.z), __float2half_rn(a.w));
    hi[i] = make_uint2(*(uint32_t*)&hA, *(uint32_t*)&hB);
}

// ---------------------------------------------------------------------------
// softmax over S axis * v, scattered transposed, emitted fp16.
// b_off selects a batch-half (0 or 32).
__global__ void __launch_bounds__(128)
softmax_mul_scatter(const float* __restrict__ S, const float* __restrict__ V,
                    __half* __restrict__ Yh, int b_off)
{
    const int b = blockIdx.y + b_off;      // n*H + h  (0..63)
    const int n = b / HH, h = b % HH;
    const int c = blockIdx.x * 128 + threadIdx.x;

    const float* Sp = S + (long long)b * BSTR;
    const float* Vp = V + (long long)b * BSTR;

    float mx = -INFINITY, sum = 0.f;
    for (int s = 0; s < SS; s++) {
        float v  = Sp[(long long)s * SS + c];
        float m2 = fmaxf(mx, v);
        sum = sum * __expf(mx - m2) + __expf(v - m2);
        mx  = m2;
    }
    const float inv = 1.f / sum;

    __half* Yhp = Yh + (long long)n * SS * DD + (long long)h * HD_ + c;
    for (int s = 0; s < SS; s++) {
        float a = __expf(Sp[(long long)s * SS + c] - mx) * inv;
        float y = a * Vp[(long long)s * SS + c];
        Yhp[(long long)s * DD] = __float2half_rn(y);
    }
}

// ---------------------------------------------------------------------------
extern "C" void kernel_launch(void* const* d_in, const int* in_sizes, int n_in,
                              void* d_out, int out_size)
{
    const float* query = (const float*)d_in[0];
    const float* key   = (const float*)d_in[1];
    const float* value = (const float*)d_in[2];
    const float* Wq    = (const float*)d_in[3];
    const float* bq    = (const float*)d_in[4];
    const float* Wk    = (const float*)d_in[5];
    const float* bk    = (const float*)d_in[6];
    const float* Wv    = (const float*)d_in[7];
    const float* bv    = (const float*)d_in[8];
    const float* Wo    = (const float*)d_in[9];
    const float* bo    = (const float*)d_in[10];
    float* out = (float*)d_out;

    float *v, *s;
    __nv_bfloat16 *qa_h,*qa_l,*ka_h,*ka_l,*wq_h,*wq_l,*wk_h,*wk_l,*q_h,*q_l,*k_h,*k_l;
    __half *va,*wv,*wo,*y_h;
    cudaGetSymbolAddress((void**)&v, g_v);     cudaGetSymbolAddress((void**)&s, g_s);
    cudaGetSymbolAddress((void**)&qa_h, g_qa_h); cudaGetSymbolAddress((void**)&qa_l, g_qa_l);
    cudaGetSymbolAddress((void**)&ka_h, g_ka_h); cudaGetSymbolAddress((void**)&ka_l, g_ka_l);
    cudaGetSymbolAddress((void**)&wq_h, g_wq_h); cudaGetSymbolAddress((void**)&wq_l, g_wq_l);
    cudaGetSymbolAddress((void**)&wk_h, g_wk_h); cudaGetSymbolAddress((void**)&wk_l, g_wk_l);
    cudaGetSymbolAddress((void**)&q_h, g_q_h);   cudaGetSymbolAddress((void**)&q_l, g_q_l);
    cudaGetSymbolAddress((void**)&k_h, g_k_h);   cudaGetSymbolAddress((void**)&k_l, g_k_l);
    cudaGetSymbolAddress((void**)&va, g_va);     cudaGetSymbolAddress((void**)&wv, g_wv);
    cudaGetSymbolAddress((void**)&wo, g_wo);
    cudaGetSymbolAddress((void**)&y_h, g_y_h);

    const int SM_330 = 3 * 65536;   // 3-pass: 64KB x3 = 192KB, 1 CTA/SM
    const int SM_110 = 3 * 32768;   // 1-pass: 32KB x3 = 96KB, 2 CTA/SM
    cudaFuncSetAttribute((const void*)gemm_tc<true,true,false,1>,
                         cudaFuncAttributeMaxDynamicSharedMemorySize, SM_330);
    cudaFuncSetAttribute((const void*)gemm_tc<false,false,true,2>,
                         cudaFuncAttributeMaxDynamicSharedMemorySize, SM_110);

    const int n4 = NELT / 4;
    const int sg = (n4 + 255) / 256;
    const dim3 gp(DD / BN, MT / BM, 1);         // 32 x 32, projections
    const dim3 gs(SS / BN, SS / BM, NB * HH);   // 4 x 4 x 64, scores (FULL)
    const dim3 goh(DD / BN, 16, 1);             // gemmO half: 32x16 (2048 rows)

    cudaStream_t s1 = g_sx.s1;

    // fork
    cudaEventRecord(g_sx.ef, 0);
    cudaStreamWaitEvent(s1, g_sx.ef, 0);

    // s1: Wq split first (off s0's critical path), then K-side, V-side, Wo
    split2_bf16<<<sg, 256, 0, s1>>>((const float4*)Wq, (uint2*)wq_h, (uint2*)wq_l, n4);
    cudaEventRecord(g_sx.eWq, s1);
    split2_bf16<<<sg, 256, 0, s1>>>((const float4*)key, (uint2*)ka_h, (uint2*)ka_l, n4);
    split2_bf16<<<sg, 256, 0, s1>>>((const float4*)Wk,  (uint2*)wk_h, (uint2*)wk_l, n4);
    cudaEventRecord(g_sx.ek, s1);
    split1_f16 <<<sg, 256, 0, s1>>>((const float4*)value, (uint2*)va, n4);
    split1_f16 <<<sg, 256, 0, s1>>>((const float4*)Wv,    (uint2*)wv, n4);
    gemm_tc<false,false,true,2><<<gp, 256, SM_110, s1>>>(
        (const uint16_t*)va, nullptr, (const uint16_t*)wv, nullptr,
        v, nullptr, nullptr, bv, DD, DD, 0, 0, 0, 1.f);
    cudaEventRecord(g_sx.ev, s1);
    split1_f16 <<<sg, 256, 0, s1>>>((const float4*)Wo, (uint2*)wo, n4);
    cudaEventRecord(g_sx.ewo, s1);

    // s0: query split -> gemmQ (waits Wq split) -> gemmK (waits K splits)
    split2_bf16<<<sg, 256>>>((const float4*)query, (uint2*)qa_h, (uint2*)qa_l, n4);
    cudaStreamWaitEvent(0, g_sx.eWq, 0);
    gemm_tc<true,true,false,1><<<gp, 256, SM_330>>>(
        (const uint16_t*)qa_h, (const uint16_t*)qa_l,
        (const uint16_t*)wq_h, (const uint16_t*)wq_l,
        nullptr, q_h, q_l, bq, DD, DD, 0, 0, 0, 1.f);
    cudaStreamWaitEvent(0, g_sx.ek, 0);
    gemm_tc<true,true,false,1><<<gp, 256, SM_330>>>(
        (const uint16_t*)ka_h, (const uint16_t*)ka_l,
        (const uint16_t*)wk_h, (const uint16_t*)wk_l,
        nullptr, k_h, k_l, bk, DD, DD, 0, 0, 0, 1.f);
    // s0: scores FULL (single 1024-CTA launch, serial after gemmK)
    gemm_tc<true,true,false,1><<<gs, 256, SM_330>>>(
        (const uint16_t*)q_h, (const uint16_t*)q_l,
        (const uint16_t*)k_h, (const uint16_t*)k_l,
        s, nullptr, nullptr, nullptr, SS, SS, BSTR, BSTR, BSTR,
        0.04419417382415922f);
    cudaEventRecord(g_sx.esc, 0);

    // tail halves: A on s0, B on s1 (softmax || fp16-GEMM; fp16 || fp16)
    // s0: softmaxA (scores in-stream; v via ev) -> gemmO_A (Wo via ewo)
    cudaStreamWaitEvent(0, g_sx.ev, 0);
    softmax_mul_scatter<<<dim3(4, 32), 128>>>(s, v, y_h, 0);
    cudaStreamWaitEvent(0, g_sx.ewo, 0);
    gemm_tc<false,false,true,2><<<goh, 256, SM_110>>>(
        (const uint16_t*)y_h, nullptr, (const uint16_t*)wo, nullptr,
        out, nullptr, nullptr, bo, DD, DD, 0, 0, 0, 1.f);
    // s1: softmaxB (scores via esc; v, wo in-stream) -> gemmO_B
    cudaStreamWaitEvent(s1, g_sx.esc, 0);
    softmax_mul_scatter<<<dim3(4, 32), 128, 0, s1>>>(s, v, y_h, 32);
    gemm_tc<false,false,true,2><<<goh, 256, SM_110, s1>>>(
        (const uint16_t*)(y_h + (long long)2048 * DD), nullptr,
        (const uint16_t*)wo, nullptr,
        out + (long long)2048 * DD, nullptr, nullptr, bo, DD, DD, 0, 0, 0, 1.f);
    cudaEventRecord(g_sx.eoB, s1);
    // join
    cudaStreamWaitEvent(0, g_sx.eoB, 0);
}

// round 14
// speedup vs baseline: 1.5365x; 1.5365x over previous
#include <cuda_runtime.h>
#include <cuda_bf16.h>
#include <cuda_fp16.h>
#include <math.h>
#include <stdint.h>

// Problem constants
#define NB   8
#define SS   512
#define DD   4096
#define HH   8
#define HD_  512
#define MT   (NB*SS)            // 4096
#define BSTR ((long long)SS*SS) // 262144
#define NELT (MT*DD)            // 16,777,216

// ---------------- scratch (device globals; allocation-guard safe) -----------
__device__ float g_v[NELT];             // V projection (fp32)
__device__ float g_s[NELT];             // scores (fp32)
__device__ __nv_bfloat16 g_qa_h[NELT], g_qa_l[NELT];
__device__ __nv_bfloat16 g_ka_h[NELT], g_ka_l[NELT];
__device__ __nv_bfloat16 g_wq_h[NELT], g_wq_l[NELT];
__device__ __nv_bfloat16 g_wk_h[NELT], g_wk_l[NELT];
__device__ __nv_bfloat16 g_q_h [NELT], g_q_l [NELT];
__device__ __nv_bfloat16 g_k_h [NELT], g_k_l [NELT];
__device__ __half g_va[NELT];
__device__ __half g_wv[NELT];
__device__ __half g_wo[NELT];
__device__ __half g_y_h[NELT];          // Y2 fp16 (hi only)

// ---------------- stream/event resources (static init, pre-checkpoint) ------
struct HxStreams {
    cudaStream_t s1;
    cudaEvent_t ef, ek, ev, ewo, esc, eoB;
    HxStreams() {
        cudaStreamCreateWithFlags(&s1, cudaStreamNonBlocking);
        cudaEventCreateWithFlags(&ef,  cudaEventDisableTiming);
        cudaEventCreateWithFlags(&ek,  cudaEventDisableTiming);
        cudaEventCreateWithFlags(&ev,  cudaEventDisableTiming);
        cudaEventCreateWithFlags(&ewo, cudaEventDisableTiming);
        cudaEventCreateWithFlags(&esc, cudaEventDisableTiming);
        cudaEventCreateWithFlags(&eoB, cudaEventDisableTiming);
    }
};
static HxStreams g_sx;

// ---------------- PTX helpers (compute_103-baseline legal) ------------------
__device__ __forceinline__ uint32_t smem_u32(const void* p) {
    uint32_t a;
    asm("{ .reg .u64 t; cvta.to.shared.u64 t, %1; cvt.u32.u64 %0, t; }"
        : "=r"(a) : "l"(p));
    return a;
}
__device__ __forceinline__ void cp16(uint32_t s, const void* g) {
    asm volatile("cp.async.cg.shared.global [%0], [%1], 16;" :: "r"(s), "l"(g));
}
__device__ __forceinline__ void cp_commit() {
    asm volatile("cp.async.commit_group;");
}
template <int N> __device__ __forceinline__ void cp_wait() {
    asm volatile("cp.async.wait_group %0;" :: "n"(N));
}
__device__ __forceinline__ void ldsm4(uint32_t& r0, uint32_t& r1,
                                      uint32_t& r2, uint32_t& r3, uint32_t a) {
    asm volatile("ldmatrix.sync.aligned.m8n8.x4.shared.b16 {%0,%1,%2,%3}, [%4];"
                 : "=r"(r0), "=r"(r1), "=r"(r2), "=r"(r3) : "r"(a));
}
template<bool FP16>
__device__ __forceinline__ void mma16816(float* d, const uint32_t* a,
                                         uint32_t b0, uint32_t b1) {
    if constexpr (FP16) {
        asm("mma.sync.aligned.m16n8k16.row.col.f32.f16.f16.f32 "
            "{%0,%1,%2,%3}, {%4,%5,%6,%7}, {%8,%9}, {%0,%1,%2,%3};"
            : "+f"(d[0]), "+f"(d[1]), "+f"(d[2]), "+f"(d[3])
            : "r"(a[0]), "r"(a[1]), "r"(a[2]), "r"(a[3]), "r"(b0), "r"(b1));
    } else {
        asm("mma.sync.aligned.m16n8k16.row.col.f32.bf16.bf16.f32 "
            "{%0,%1,%2,%3}, {%4,%5,%6,%7}, {%8,%9}, {%0,%1,%2,%3};"
            : "+f"(d[0]), "+f"(d[1]), "+f"(d[2]), "+f"(d[3])
            : "r"(a[0]), "r"(a[1]), "r"(a[2]), "r"(a[3]), "r"(b0), "r"(b1));
    }
}

// ---------------- tile constants --------------------------------------------
#define BM 128
#define BN 128
#define BK 64
// SW128 layout: 128B per row (64 x b16). row r, 16B chunk c:
// byte = r*128 + ((c*16) ^ ((r&7)<<4)).

// ---------------------------------------------------------------------------
// HMMA NT GEMM: C = scale * A B^T (+ bias).  Passes: AhBh [+ AhBl][+ AlBh].
// ---------------------------------------------------------------------------
template<bool HAS_AL, bool HAS_BL, bool FP16, int MINB>
__global__ void __launch_bounds__(256, MINB)
gemm_tc(const uint16_t* __restrict__ Ah, const uint16_t* __restrict__ Al,
        const uint16_t* __restrict__ Bh, const uint16_t* __restrict__ Bl,
        float* __restrict__ C, __nv_bfloat16* __restrict__ Ch,
        __nv_bfloat16* __restrict__ Cl, const float* __restrict__ bias,
        int Nn, int Kk, long long sA, long long sB, long long sC, float scale)
{
    constexpr uint32_t SZ_A = 128 * 128;    // 16KB
    constexpr uint32_t SZ_B = 128 * 128;    // 16KB
    constexpr uint32_t OFF_BH = SZ_A * (1 + (HAS_AL ? 1 : 0));
    constexpr uint32_t STG_SZ = SZ_A * (1 + (HAS_AL ? 1 : 0))
                              + SZ_B * (1 + (HAS_BL ? 1 : 0));
    constexpr int STAGES = 3;

    extern __shared__ __align__(1024) char smem[];
    const uint32_t sb = smem_u32(smem);
    const int tid = threadIdx.x;
    const int bz = blockIdx.z;
    Ah += (long long)bz * sA;  if (HAS_AL) Al += (long long)bz * sA;
    Bh += (long long)bz * sB;  if (HAS_BL) Bl += (long long)bz * sB;

    const int m0 = blockIdx.y * BM;
    const int n0 = blockIdx.x * BN;
    const int nst = Kk / BK;

    auto load_stage = [&](int s, int buf) {
        const uint32_t stg = sb + (uint32_t)buf * STG_SZ;
        const int kk = s * BK;
        #pragma unroll
        for (int it = 0; it < 4; it++) {
            int id = tid + it * 256;
            int r = id >> 3, c = id & 7;
            long long go = (long long)(m0 + r) * Kk + kk + c * 8;
            uint32_t so = (uint32_t)(r * 128 + ((c * 16) ^ ((r & 7) << 4)));
            cp16(stg + so, Ah + go);
            if (HAS_AL) cp16(stg + SZ_A + so, Al + go);
        }
        #pragma unroll
        for (int it = 0; it < 4; it++) {
            int id = tid + it * 256;
            int r = id >> 3, c = id & 7;
            long long go = (long long)(n0 + r) * Kk + kk + c * 8;
            uint32_t so = (uint32_t)(r * 128 + ((c * 16) ^ ((r & 7) << 4)));
            cp16(stg + OFF_BH + so, Bh + go);
            if (HAS_BL) cp16(stg + OFF_BH + SZ_B + so, Bl + go);
        }
    };

    // 2x4 warps, warp tile 64x32
    const int wid = tid >> 5, lane = tid & 31;
    const int warp_m = wid & 1;
    const int warp_n = wid >> 1;
    const int arow0 = warp_m * 64 + (lane & 15);
    const int brow0 = warp_n * 32 + (lane & 15);
    const uint32_t halfsel = (uint32_t)((lane >> 4) * 16);

    float acc[4][4][4];
    #pragma unroll
    for (int i = 0; i < 4; i++)
        #pragma unroll
        for (int j = 0; j < 4; j++)
            #pragma unroll
            for (int k = 0; k < 4; k++) acc[i][j][k] = 0.f;

    #pragma unroll
    for (int s = 0; s < STAGES - 1; s++) {
        if (s < nst) { load_stage(s, s); cp_commit(); }
    }

    for (int c = 0; c < nst; c++) {
        cp_wait<STAGES - 2>();
        __syncthreads();
        if (c + STAGES - 1 < nst) {
            load_stage(c + STAGES - 1, (c + STAGES - 1) % STAGES);
            cp_commit();
        }
        const uint32_t stg = sb + (uint32_t)(c % STAGES) * STG_SZ;

        #pragma unroll
        for (int ks = 0; ks < 4; ks++) {
            const uint32_t ko = (uint32_t)(ks * 32);
            uint32_t ah[4][4], al[4][4];
            #pragma unroll
            for (int mt = 0; mt < 4; mt++) {
                int row = arow0 + mt * 16;
                uint32_t ad = stg + (uint32_t)row * 128
                            + ((ko + halfsel) ^ (uint32_t)((row & 7) << 4));
                ldsm4(ah[mt][0], ah[mt][1], ah[mt][2], ah[mt][3], ad);
                if (HAS_AL)
                    ldsm4(al[mt][0], al[mt][1], al[mt][2], al[mt][3], ad + SZ_A);
            }
            #pragma unroll
            for (int g = 0; g < 2; g++) {
                int row = brow0 + g * 16;
                uint32_t bd = stg + OFF_BH + (uint32_t)row * 128
                            + ((ko + halfsel) ^ (uint32_t)((row & 7) << 4));
                uint32_t bh[4], bl[4];
                ldsm4(bh[0], bh[1], bh[2], bh[3], bd);
                if (HAS_BL) ldsm4(bl[0], bl[1], bl[2], bl[3], bd + SZ_B);
                #pragma unroll
                for (int half = 0; half < 2; half++) {
                    const int nt = g * 2 + half;
                    const uint32_t b0h = bh[half], b1h = bh[half + 2];
                    #pragma unroll
                    for (int mt = 0; mt < 4; mt++) {
                        mma16816<FP16>(acc[mt][nt], ah[mt], b0h, b1h);
                        if (HAS_BL)
                            mma16816<FP16>(acc[mt][nt], ah[mt], bl[half], bl[half + 2]);
                        if (HAS_AL)
                            mma16816<FP16>(acc[mt][nt], al[mt], b0h, b1h);
                    }
                }
            }
        }
    }

    // ---- epilogue --------------------------------------------------------
    const int r0 = lane >> 2;
    const int c0 = (lane & 3) * 2;
    float* Cp = C ? (C + (long long)bz * sC) : nullptr;
    __nv_bfloat16* Chp = Ch ? (Ch + (long long)bz * sC) : nullptr;
    __nv_bfloat16* Clp = Cl ? (Cl + (long long)bz * sC) : nullptr;

    #pragma unroll
    for (int mt = 0; mt < 4; mt++) {
        #pragma unroll
        for (int nt = 0; nt < 4; nt++) {
            const int gc = n0 + warp_n * 32 + nt * 8 + c0;
            float b0 = 0.f, b1 = 0.f;
            if (bias) { b0 = __ldg(&bias[gc]); b1 = __ldg(&bias[gc + 1]); }
            #pragma unroll
            for (int hh = 0; hh < 2; hh++) {
                const int gr = m0 + warp_m * 64 + mt * 16 + r0 + hh * 8;
                float v0 = acc[mt][nt][hh * 2 + 0] * scale + b0;
                float v1 = acc[mt][nt][hh * 2 + 1] * scale + b1;
                if (Cp) {
                    float2 o = make_float2(v0, v1);
                    *(float2*)(Cp + (long long)gr * Nn + gc) = o;
                }
                if (Chp) {
                    __nv_bfloat16 h0 = __float2bfloat16(v0);
                    __nv_bfloat16 h1 = __float2bfloat16(v1);
                    __nv_bfloat16 l0 = __float2bfloat16(v0 - __bfloat162float(h0));
                    __nv_bfloat16 l1 = __float2bfloat16(v1 - __bfloat162float(h1));
                    __nv_bfloat162 hp(h0, h1), lp(l0, l1);
                    *(uint32_t*)(Chp + (long long)gr * Nn + gc) = *(uint32_t*)&hp;
                    *(uint32_t*)(Clp + (long long)gr * Nn + gc) = *(uint32_t*)&lp;
                }
            }
        }
    }
}

// ---------------------------------------------------------------------------
// fp32 -> bf16 hi/lo split
__global__ void __launch_bounds__(256)
split2_bf16(const float4* __restrict__ in, uint2* __restrict__ hi,
            uint2* __restrict__ lo, int n4)
{
    int i = blockIdx.x * blockDim.x + threadIdx.x;
    if (i >= n4) return;
    float4 a = in[i];
    __nv_bfloat16 h0 = __float2bfloat16(a.x), h1 = __float2bfloat16(a.y);
    __nv_bfloat16 h2 = __float2bfloat16(a.z), h3 = __float2bfloat16(a.w);
    __nv_bfloat16 l0 = __float2bfloat16(a.x - __bfloat162float(h0));
    __nv_bfloat16 l1 = __float2bfloat16(a.y - __bfloat162float(h1));
    __nv_bfloat16 l2 = __float2bfloat16(a.z - __bfloat162float(h2));
    __nv_bfloat16 l3 = __float2bfloat16(a.w - __bfloat162float(h3));
    __nv_bfloat162 hA(h0, h1), hB(h2, h3), lA(l0, l1), lB(l2, l3);
    hi[i] = make_uint2(*(uint32_t*)&hA, *(uint32_t*)&hB);
    lo[i] = make_uint2(*(uint32_t*)&lA, *(uint32_t*)&lB);
}

// fp32 -> fp16
__global__ void __launch_bounds__(256)
split1_f16(const float4* __restrict__ in, uint2* __restrict__ hi, int n4)
{
    int i = blockIdx.x * blockDim.x + threadIdx.x;
    if (i >= n4) return;
    float4 a = in[i];
    __half2 hA(__float2half_rn(a.x), __float2half_rn(a.y));
    __half2 hB(__float2half_rn(a.z), __float2half_rn(a.w));
    hi[i] = make_uint2(*(uint32_t*)&hA, *(uint32_t*)&hB);
}

// ---------------------------------------------------------------------------
// softmax over S axis * v, scattered transposed, emitted fp16.
// b_off selects a batch-half (0 or 32).
__global__ void __launch_bounds__(128)
softmax_mul_scatter(const float* __restrict__ S, const float* __restrict__ V,
                    __half* __restrict__ Yh, int b_off)
{
    const int b = blockIdx.y + b_off;      // n*H + h  (0..63)
    const int n = b / HH, h = b % HH;
    const int c = blockIdx.x * 128 + threadIdx.x;

    const float* Sp = S + (long long)b * BSTR;
    const float* Vp = V + (long long)b * BSTR;

    float mx = -INFINITY, sum = 0.f;
    for (int s = 0; s < SS; s++) {
        float v  = Sp[(long long)s * SS + c];
        float m2 = fmaxf(mx, v);
        sum = sum * __expf(mx - m2) + __expf(v - m2);
        mx  = m2;
    }
    const float inv = 1.f / sum;

    __half* Yhp = Yh + (long long)n * SS * DD + (long long)h * HD_ + c;
    for (int s = 0; s < SS; s++) {
        float a = __expf(Sp[(long long)s * SS + c] - mx) * inv;
        float y = a * Vp[(long long)s * SS + c];
        Yhp[(long long)s * DD] = __float2half_rn(y);
    }
}

// ---------------------------------------------------------------------------
extern "C" void kernel_launch(void* const* d_in, const int* in_sizes, int n_in,
                              void* d_out, int out_size)
{
    const float* query = (const float*)d_in[0];
    const float* key   = (const float*)d_in[1];
    const float* value = (const float*)d_in[2];
    const float* Wq    = (const float*)d_in[3];
    const float* bq    = (const float*)d_in[4];
    const float* Wk    = (const float*)d_in[5];
    const float* bk    = (const float*)d_in[6];
    const float* Wv    = (const float*)d_in[7];
    const float* bv    = (const float*)d_in[8];
    const float* Wo    = (const float*)d_in[9];
    const float* bo    = (const float*)d_in[10];
    float* out = (float*)d_out;

    float *v, *s;
    __nv_bfloat16 *qa_h,*qa_l,*ka_h,*ka_l,*wq_h,*wq_l,*wk_h,*wk_l,*q_h,*q_l,*k_h,*k_l;
    __half *va,*wv,*wo,*y_h;
    cudaGetSymbolAddress((void**)&v, g_v);     cudaGetSymbolAddress((void**)&s, g_s);
    cudaGetSymbolAddress((void**)&qa_h, g_qa_h); cudaGetSymbolAddress((void**)&qa_l, g_qa_l);
    cudaGetSymbolAddress((void**)&ka_h, g_ka_h); cudaGetSymbolAddress((void**)&ka_l, g_ka_l);
    cudaGetSymbolAddress((void**)&wq_h, g_wq_h); cudaGetSymbolAddress((void**)&wq_l, g_wq_l);
    cudaGetSymbolAddress((void**)&wk_h, g_wk_h); cudaGetSymbolAddress((void**)&wk_l, g_wk_l);
    cudaGetSymbolAddress((void**)&q_h, g_q_h);   cudaGetSymbolAddress((void**)&q_l, g_q_l);
    cudaGetSymbolAddress((void**)&k_h, g_k_h);   cudaGetSymbolAddress((void**)&k_l, g_k_l);
    cudaGetSymbolAddress((void**)&va, g_va);     cudaGetSymbolAddress((void**)&wv, g_wv);
    cudaGetSymbolAddress((void**)&wo, g_wo);
    cudaGetSymbolAddress((void**)&y_h, g_y_h);

    const int SM_330 = 3 * 65536;   // 3-pass: 64KB x3 = 192KB, 1 CTA/SM
    const int SM_110 = 3 * 32768;   // 1-pass: 32KB x3 = 96KB, 2 CTA/SM
    cudaFuncSetAttribute((const void*)gemm_tc<true,true,false,1>,
                         cudaFuncAttributeMaxDynamicSharedMemorySize, SM_330);
    cudaFuncSetAttribute((const void*)gemm_tc<false,false,true,2>,
                         cudaFuncAttributeMaxDynamicSharedMemorySize, SM_110);

    const int n4 = NELT / 4;
    const int sg = (n4 + 255) / 256;
    const dim3 gp(DD / BN, MT / BM, 1);         // 32 x 32, projections
    const dim3 gs(SS / BN, SS / BM, NB * HH);   // 4 x 4 x 64, scores (FULL)
    const dim3 goh(DD / BN, 16, 1);             // gemmO half: 32x16 (2048 rows)

    cudaStream_t s1 = g_sx.s1;

    // ---- fork side stream (R10 head, verbatim) ---------------------------
    cudaEventRecord(g_sx.ef, 0);
    cudaStreamWaitEvent(s1, g_sx.ef, 0);

    // Side stream: K-input splits -> ek; V splits -> gemmV -> ev; Wo split -> ewo
    split2_bf16<<<sg, 256, 0, s1>>>((const float4*)key, (uint2*)ka_h, (uint2*)ka_l, n4);
    split2_bf16<<<sg, 256, 0, s1>>>((const float4*)Wk,  (uint2*)wk_h, (uint2*)wk_l, n4);
    cudaEventRecord(g_sx.ek, s1);
    split1_f16 <<<sg, 256, 0, s1>>>((const float4*)value, (uint2*)va, n4);
    split1_f16 <<<sg, 256, 0, s1>>>((const float4*)Wv,    (uint2*)wv, n4);
    gemm_tc<false,false,true,2><<<gp, 256, SM_110, s1>>>(
        (const uint16_t*)va, nullptr, (const uint16_t*)wv, nullptr,
        v, nullptr, nullptr, bv, DD, DD, 0, 0, 0, 1.f);
    cudaEventRecord(g_sx.ev, s1);
    split1_f16 <<<sg, 256, 0, s1>>>((const float4*)Wo, (uint2*)wo, n4);
    cudaEventRecord(g_sx.ewo, s1);

    // Main stream: Q splits -> gemmQ -> gemmK -> scores (R10 head, verbatim)
    split2_bf16<<<sg, 256>>>((const float4*)query, (uint2*)qa_h, (uint2*)qa_l, n4);
    split2_bf16<<<sg, 256>>>((const float4*)Wq,    (uint2*)wq_h, (uint2*)wq_l, n4);
    gemm_tc<true,true,false,1><<<gp, 256, SM_330>>>(
        (const uint16_t*)qa_h, (const uint16_t*)qa_l,
        (const uint16_t*)wq_h, (const uint16_t*)wq_l,
        nullptr, q_h, q_l, bq, DD, DD, 0, 0, 0, 1.f);
    cudaStreamWaitEvent(0, g_sx.ek, 0);
    gemm_tc<true,true,false,1><<<gp, 256, SM_330>>>(
        (const uint16_t*)ka_h, (const uint16_t*)ka_l,
        (const uint16_t*)wk_h, (const uint16_t*)wk_l,
        nullptr, k_h, k_l, bk, DD, DD, 0, 0, 0, 1.f);
    gemm_tc<true,true,false,1><<<gs, 256, SM_330>>>(
        (const uint16_t*)q_h, (const uint16_t*)q_l,
        (const uint16_t*)k_h, (const uint16_t*)k_l,
        s, nullptr, nullptr, nullptr, SS, SS, BSTR, BSTR, BSTR,
        0.04419417382415922f);
    cudaEventRecord(g_sx.esc, 0);

    // ---- tail (ONLY change vs R10): halves pipelined across streams ------
    // s0: softmaxA (scores in-stream; v via ev) -> gemmO_A (Wo via ewo)
    cudaStreamWaitEvent(0, g_sx.ev, 0);
    softmax_mul_scatter<<<dim3(4, 32), 128>>>(s, v, y_h, 0);
    cudaStreamWaitEvent(0, g_sx.ewo, 0);
    gemm_tc<false,false,true,2><<<goh, 256, SM_110>>>(
        (const uint16_t*)y_h, nullptr, (const uint16_t*)wo, nullptr,
        out, nullptr, nullptr, bo, DD, DD, 0, 0, 0, 1.f);
    // s1: softmaxB (scores via esc; v, wo in-stream) -> gemmO_B
    cudaStreamWaitEvent(s1, g_sx.esc, 0);
    softmax_mul_scatter<<<dim3(4, 32), 128, 0, s1>>>(s, v, y_h, 32);
    gemm_tc<false,false,true,2><<<goh, 256, SM_110, s1>>>(
        (const uint16_t*)(y_h + (long long)2048 * DD), nullptr,
        (const uint16_t*)wo, nullptr,
        out + (long long)2048 * DD, nullptr, nullptr, bo, DD, DD, 0, 0, 0, 1.f);
    cudaEventRecord(g_sx.eoB, s1);
    // join
    cudaStreamWaitEvent(0, g_sx.eoB, 0);
}

// round 15
// speedup vs baseline: 1.5714x; 1.0228x over previous
#include <cuda_runtime.h>
#include <cuda_bf16.h>
#include <cuda_fp16.h>
#include <math.h>
#include <stdint.h>

// Problem constants
#define NB   8
#define SS   512
#define DD   4096
#define HH   8
#define HD_  512
#define MT   (NB*SS)            // 4096
#define BSTR ((long long)SS*SS) // 262144
#define NELT (MT*DD)            // 16,777,216

// ---------------- scratch (device globals; allocation-guard safe) -----------
__device__ float g_v[NELT];
__device__ float g_s[NELT];
__device__ __nv_bfloat16 g_qa_h[NELT], g_qa_l[NELT];
__device__ __nv_bfloat16 g_ka_h[NELT], g_ka_l[NELT];
__device__ __nv_bfloat16 g_wq_h[NELT], g_wq_l[NELT];
__device__ __nv_bfloat16 g_wk_h[NELT], g_wk_l[NELT];
__device__ __nv_bfloat16 g_q_h [NELT], g_q_l [NELT];
__device__ __nv_bfloat16 g_k_h [NELT], g_k_l [NELT];
__device__ __half g_va[NELT];
__device__ __half g_wv[NELT];
__device__ __half g_wo[NELT];
__device__ __half g_y_h[NELT];

// ---------------- stream/event resources (static init) ----------------------
struct HxStreams {
    cudaStream_t s1;
    cudaEvent_t ef, ek, ev, ewo, esc, eoB;
    HxStreams() {
        cudaStreamCreateWithFlags(&s1, cudaStreamNonBlocking);
        cudaEventCreateWithFlags(&ef,  cudaEventDisableTiming);
        cudaEventCreateWithFlags(&ek,  cudaEventDisableTiming);
        cudaEventCreateWithFlags(&ev,  cudaEventDisableTiming);
        cudaEventCreateWithFlags(&ewo, cudaEventDisableTiming);
        cudaEventCreateWithFlags(&esc, cudaEventDisableTiming);
        cudaEventCreateWithFlags(&eoB, cudaEventDisableTiming);
    }
};
static HxStreams g_sx;

// ---------------- PTX helpers ------------------------------------------------
__device__ __forceinline__ uint32_t smem_u32(const void* p) {
    uint32_t a;
    asm("{ .reg .u64 t; cvta.to.shared.u64 t, %1; cvt.u32.u64 %0, t; }"
        : "=r"(a) : "l"(p));
    return a;
}
__device__ __forceinline__ void cp16(uint32_t s, const void* g) {
    asm volatile("cp.async.cg.shared.global [%0], [%1], 16;" :: "r"(s), "l"(g));
}
__device__ __forceinline__ void cp_commit() {
    asm volatile("cp.async.commit_group;");
}
template <int N> __device__ __forceinline__ void cp_wait() {
    asm volatile("cp.async.wait_group %0;" :: "n"(N));
}
__device__ __forceinline__ void ldsm4(uint32_t& r0, uint32_t& r1,
                                      uint32_t& r2, uint32_t& r3, uint32_t a) {
    asm volatile("ldmatrix.sync.aligned.m8n8.x4.shared.b16 {%0,%1,%2,%3}, [%4];"
                 : "=r"(r0), "=r"(r1), "=r"(r2), "=r"(r3) : "r"(a));
}
template<bool FP16>
__device__ __forceinline__ void mma16816(float* d, const uint32_t* a,
                                         uint32_t b0, uint32_t b1) {
    if constexpr (FP16) {
        asm("mma.sync.aligned.m16n8k16.row.col.f32.f16.f16.f32 "
            "{%0,%1,%2,%3}, {%4,%5,%6,%7}, {%8,%9}, {%0,%1,%2,%3};"
            : "+f"(d[0]), "+f"(d[1]), "+f"(d[2]), "+f"(d[3])
            : "r"(a[0]), "r"(a[1]), "r"(a[2]), "r"(a[3]), "r"(b0), "r"(b1));
    } else {
        asm("mma.sync.aligned.m16n8k16.row.col.f32.bf16.bf16.f32 "
            "{%0,%1,%2,%3}, {%4,%5,%6,%7}, {%8,%9}, {%0,%1,%2,%3};"
            : "+f"(d[0]), "+f"(d[1]), "+f"(d[2]), "+f"(d[3])
            : "r"(a[0]), "r"(a[1]), "r"(a[2]), "r"(a[3]), "r"(b0), "r"(b1));
    }
}

// ---------------------------------------------------------------------------
// 3-pass bf16 NT GEMM, WIDE tile: BM=128, BN=256, BK=64, 2 stages (96KB ea).
// Warp tile 64x64 (2x4 warps): 1.5x fewer LDSM bytes per MAC than 64x32.
// C = scale * (Ah+Al)(Bh+Bl)^T (+ bias); outputs fp32 C and/or bf16 split.
// ---------------------------------------------------------------------------
__global__ void __launch_bounds__(256, 1)
gemm3_wide(const uint16_t* __restrict__ Ah, const uint16_t* __restrict__ Al,
           const uint16_t* __restrict__ Bh, const uint16_t* __restrict__ Bl,
           float* __restrict__ C, __nv_bfloat16* __restrict__ Ch,
           __nv_bfloat16* __restrict__ Cl, const float* __restrict__ bias,
           int Nn, int Kk, long long sA, long long sB, long long sC,
           float scale)
{
    constexpr uint32_t SZ_A = 128 * 128;    // 16KB per limb
    constexpr uint32_t SZ_B = 256 * 128;    // 32KB per limb
    constexpr uint32_t OFF_BH = 2 * SZ_A;   // 32KB
    constexpr uint32_t STG_SZ = 2 * SZ_A + 2 * SZ_B;  // 96KB
    constexpr int STAGES = 2;

    extern __shared__ __align__(1024) char smem[];
    const uint32_t sb = smem_u32(smem);
    const int tid = threadIdx.x;
    const int bz = blockIdx.z;
    Ah += (long long)bz * sA;  Al += (long long)bz * sA;
    Bh += (long long)bz * sB;  Bl += (long long)bz * sB;

    const int m0 = blockIdx.y * 128;
    const int n0 = blockIdx.x * 256;
    const int nst = Kk / 64;

    auto load_stage = [&](int s, int buf) {
        const uint32_t stg = sb + (uint32_t)buf * STG_SZ;
        const int kk = s * 64;
        #pragma unroll
        for (int it = 0; it < 4; it++) {          // A: 128 rows x 8 chunks
            int id = tid + it * 256;
            int r = id >> 3, c = id & 7;
            long long go = (long long)(m0 + r) * Kk + kk + c * 8;
            uint32_t so = (uint32_t)(r * 128 + ((c * 16) ^ ((r & 7) << 4)));
            cp16(stg + so, Ah + go);
            cp16(stg + SZ_A + so, Al + go);
        }
        #pragma unroll
        for (int it = 0; it < 8; it++) {          // B: 256 rows x 8 chunks
            int id = tid + it * 256;
            int r = id >> 3, c = id & 7;
            long long go = (long long)(n0 + r) * Kk + kk + c * 8;
            uint32_t so = (uint32_t)(r * 128 + ((c * 16) ^ ((r & 7) << 4)));
            cp16(stg + OFF_BH + so, Bh + go);
            cp16(stg + OFF_BH + SZ_B + so, Bl + go);
        }
    };

    // 2x4 warps, warp tile 64x64
    const int wid = tid >> 5, lane = tid & 31;
    const int warp_m = wid & 1;
    const int warp_n = wid >> 1;
    const int arow0 = warp_m * 64 + (lane & 15);
    const int brow0 = warp_n * 64 + (lane & 15);
    const uint32_t halfsel = (uint32_t)((lane >> 4) * 16);

    float acc[4][8][4];
    #pragma unroll
    for (int i = 0; i < 4; i++)
        #pragma unroll
        for (int j = 0; j < 8; j++)
            #pragma unroll
            for (int k = 0; k < 4; k++) acc[i][j][k] = 0.f;

    load_stage(0, 0); cp_commit();
    if (nst > 1) { load_stage(1, 1); cp_commit(); }

    for (int c = 0; c < nst; c++) {
        if (c + 2 < nst) cp_wait<1>(); else cp_wait<0>();
        __syncthreads();
        const uint32_t stg = sb + (uint32_t)(c & 1) * STG_SZ;

        #pragma unroll
        for (int ks = 0; ks < 4; ks++) {
            const uint32_t ko = (uint32_t)(ks * 32);
            uint32_t ah[4][4], al[4][4];
            #pragma unroll
            for (int mt = 0; mt < 4; mt++) {
                int row = arow0 + mt * 16;
                uint32_t ad = stg + (uint32_t)row * 128
                            + ((ko + halfsel) ^ (uint32_t)((row & 7) << 4));
                ldsm4(ah[mt][0], ah[mt][1], ah[mt][2], ah[mt][3], ad);
                ldsm4(al[mt][0], al[mt][1], al[mt][2], al[mt][3], ad + SZ_A);
            }
            #pragma unroll
            for (int g = 0; g < 4; g++) {
                int row = brow0 + g * 16;
                uint32_t bd = stg + OFF_BH + (uint32_t)row * 128
                            + ((ko + halfsel) ^ (uint32_t)((row & 7) << 4));
                uint32_t bh[4], bl[4];
                ldsm4(bh[0], bh[1], bh[2], bh[3], bd);
                ldsm4(bl[0], bl[1], bl[2], bl[3], bd + SZ_B);
                #pragma unroll
                for (int half = 0; half < 2; half++) {
                    const int nt = g * 2 + half;
                    const uint32_t b0h = bh[half], b1h = bh[half + 2];
                    #pragma unroll
                    for (int mt = 0; mt < 4; mt++) {
                        mma16816<false>(acc[mt][nt], ah[mt], b0h, b1h);
                        mma16816<false>(acc[mt][nt], ah[mt],
                                        bl[half], bl[half + 2]);
                        mma16816<false>(acc[mt][nt], al[mt], b0h, b1h);
                    }
                }
            }
        }
        __syncthreads();
        if (c + 2 < nst) { load_stage(c + 2, c & 1); cp_commit(); }
    }

    // epilogue
    const int r0 = lane >> 2;
    const int c0 = (lane & 3) * 2;
    float* Cp = C ? (C + (long long)bz * sC) : nullptr;
    __nv_bfloat16* Chp = Ch ? (Ch + (long long)bz * sC) : nullptr;
    __nv_bfloat16* Clp = Cl ? (Cl + (long long)bz * sC) : nullptr;

    #pragma unroll
    for (int mt = 0; mt < 4; mt++) {
        #pragma unroll
        for (int nt = 0; nt < 8; nt++) {
            const int gc = n0 + warp_n * 64 + nt * 8 + c0;
            float b0 = 0.f, b1 = 0.f;
            if (bias) { b0 = __ldg(&bias[gc]); b1 = __ldg(&bias[gc + 1]); }
            #pragma unroll
            for (int hh = 0; hh < 2; hh++) {
                const int gr = m0 + warp_m * 64 + mt * 16 + r0 + hh * 8;
                float v0 = acc[mt][nt][hh * 2 + 0] * scale + b0;
                float v1 = acc[mt][nt][hh * 2 + 1] * scale + b1;
                if (Cp) {
                    float2 o = make_float2(v0, v1);
                    *(float2*)(Cp + (long long)gr * Nn + gc) = o;
                }
                if (Chp) {
                    __nv_bfloat16 h0 = __float2bfloat16(v0);
                    __nv_bfloat16 h1 = __float2bfloat16(v1);
                    __nv_bfloat16 l0 = __float2bfloat16(v0 - __bfloat162float(h0));
                    __nv_bfloat16 l1 = __float2bfloat16(v1 - __bfloat162float(h1));
                    __nv_bfloat162 hp(h0, h1), lp(l0, l1);
                    *(uint32_t*)(Chp + (long long)gr * Nn + gc) = *(uint32_t*)&hp;
                    *(uint32_t*)(Clp + (long long)gr * Nn + gc) = *(uint32_t*)&lp;
                }
            }
        }
    }
}

// ---------------------------------------------------------------------------
// 1-pass fp16 NT GEMM (unchanged R6/R14 shape): BM=BN=128, 3x32KB, 2 CTA/SM.
// ---------------------------------------------------------------------------
__global__ void __launch_bounds__(256, 2)
gemm1_f16(const uint16_t* __restrict__ A, const uint16_t* __restrict__ B,
          float* __restrict__ C, const float* __restrict__ bias,
          int Nn, int Kk)
{
    constexpr uint32_t SZ_A = 128 * 128;    // 16KB
    constexpr uint32_t STG_SZ = 2 * SZ_A;   // 32KB
    constexpr int STAGES = 3;

    extern __shared__ __align__(1024) char smem[];
    const uint32_t sb = smem_u32(smem);
    const int tid = threadIdx.x;
    const int m0 = blockIdx.y * 128;
    const int n0 = blockIdx.x * 128;
    const int nst = Kk / 64;

    auto load_stage = [&](int s, int buf) {
        const uint32_t stg = sb + (uint32_t)buf * STG_SZ;
        const int kk = s * 64;
        #pragma unroll
        for (int it = 0; it < 4; it++) {
            int id = tid + it * 256;
            int r = id >> 3, c = id & 7;
            long long go = (long long)(m0 + r) * Kk + kk + c * 8;
            uint32_t so = (uint32_t)(r * 128 + ((c * 16) ^ ((r & 7) << 4)));
            cp16(stg + so, A + go);
        }
        #pragma unroll
        for (int it = 0; it < 4; it++) {
            int id = tid + it * 256;
            int r = id >> 3, c = id & 7;
            long long go = (long long)(n0 + r) * Kk + kk + c * 8;
            uint32_t so = (uint32_t)(r * 128 + ((c * 16) ^ ((r & 7) << 4)));
            cp16(stg + SZ_A + so, B + go);
        }
    };

    const int wid = tid >> 5, lane = tid & 31;
    const int warp_m = wid & 1;
    const int warp_n = wid >> 1;
    const int arow0 = warp_m * 64 + (lane & 15);
    const int brow0 = warp_n * 32 + (lane & 15);
    const uint32_t halfsel = (uint32_t)((lane >> 4) * 16);

    float acc[4][4][4];
    #pragma unroll
    for (int i = 0; i < 4; i++)
        #pragma unroll
        for (int j = 0; j < 4; j++)
            #pragma unroll
            for (int k = 0; k < 4; k++) acc[i][j][k] = 0.f;

    #pragma unroll
    for (int s = 0; s < STAGES - 1; s++) {
        if (s < nst) { load_stage(s, s); cp_commit(); }
    }

    for (int c = 0; c < nst; c++) {
        cp_wait<STAGES - 2>();
        __syncthreads();
        if (c + STAGES - 1 < nst) {
            load_stage(c + STAGES - 1, (c + STAGES - 1) % STAGES);
            cp_commit();
        }
        const uint32_t stg = sb + (uint32_t)(c % STAGES) * STG_SZ;

        #pragma unroll
        for (int ks = 0; ks < 4; ks++) {
            const uint32_t ko = (uint32_t)(ks * 32);
            uint32_t ah[4][4];
            #pragma unroll
            for (int mt = 0; mt < 4; mt++) {
                int row = arow0 + mt * 16;
                uint32_t ad = stg + (uint32_t)row * 128
                            + ((ko + halfsel) ^ (uint32_t)((row & 7) << 4));
                ldsm4(ah[mt][0], ah[mt][1], ah[mt][2], ah[mt][3], ad);
            }
            #pragma unroll
            for (int g = 0; g < 2; g++) {
                int row = brow0 + g * 16;
                uint32_t bd = stg + SZ_A + (uint32_t)row * 128
                            + ((ko + halfsel) ^ (uint32_t)((row & 7) << 4));
                uint32_t bh[4];
                ldsm4(bh[0], bh[1], bh[2], bh[3], bd);
                #pragma unroll
                for (int half = 0; half < 2; half++) {
                    const int nt = g * 2 + half;
                    #pragma unroll
                    for (int mt = 0; mt < 4; mt++)
                        mma16816<true>(acc[mt][nt], ah[mt],
                                       bh[half], bh[half + 2]);
                }
            }
        }
    }

    const int r0 = lane >> 2;
    const int c0 = (lane & 3) * 2;
    #pragma unroll
    for (int mt = 0; mt < 4; mt++) {
        #pragma unroll
        for (int nt = 0; nt < 4; nt++) {
            const int gc = n0 + warp_n * 32 + nt * 8 + c0;
            float b0 = 0.f, b1 = 0.f;
            if (bias) { b0 = __ldg(&bias[gc]); b1 = __ldg(&bias[gc + 1]); }
            #pragma unroll
            for (int hh = 0; hh < 2; hh++) {
                const int gr = m0 + warp_m * 64 + mt * 16 + r0 + hh * 8;
                float2 o = make_float2(acc[mt][nt][hh * 2 + 0] + b0,
                                       acc[mt][nt][hh * 2 + 1] + b1);
                *(float2*)(C + (long long)gr * Nn + gc) = o;
            }
        }
    }
}

// ---------------------------------------------------------------------------
// fp32 -> bf16 hi/lo split
__global__ void __launch_bounds__(256)
split2_bf16(const float4* __restrict__ in, uint2* __restrict__ hi,
            uint2* __restrict__ lo, int n4)
{
    int i = blockIdx.x * blockDim.x + threadIdx.x;
    if (i >= n4) return;
    float4 a = in[i];
    __nv_bfloat16 h0 = __float2bfloat16(a.x), h1 = __float2bfloat16(a.y);
    __nv_bfloat16 h2 = __float2bfloat16(a.z), h3 = __float2bfloat16(a.w);
    __nv_bfloat16 l0 = __float2bfloat16(a.x - __bfloat162float(h0));
    __nv_bfloat16 l1 = __float2bfloat16(a.y - __bfloat162float(h1));
    __nv_bfloat16 l2 = __float2bfloat16(a.z - __bfloat162float(h2));
    __nv_bfloat16 l3 = __float2bfloat16(a.w - __bfloat162float(h3));
    __nv_bfloat162 hA(h0, h1), hB(h2, h3), lA(l0, l1), lB(l2, l3);
    hi[i] = make_uint2(*(uint32_t*)&hA, *(uint32_t*)&hB);
    lo[i] = make_uint2(*(uint32_t*)&lA, *(uint32_t*)&lB);
}

// fp32 -> fp16
__global__ void __launch_bounds__(256)
split1_f16(const float4* __restrict__ in, uint2* __restrict__ hi, int n4)
{
    int i = blockIdx.x * blockDim.x + threadIdx.x;
    if (i >= n4) return;
    float4 a = in[i];
    __half2 hA(__float2half_rn(a.x), __float2half_rn(a.y));
    __half2 hB(__float2half_rn(a.z), __float2half_rn(a.w));
    hi[i] = make_uint2(*(uint32_t*)&hA, *(uint32_t*)&hB);
}

// ---------------------------------------------------------------------------
// softmax over S axis * v, scattered transposed, emitted fp16. b_off: 0 or 32.
__global__ void __launch_bounds__(128)
softmax_mul_scatter(const float* __restrict__ S, const float* __restrict__ V,
                    __half* __restrict__ Yh, int b_off)
{
    const int b = blockIdx.y + b_off;
    const int n = b / HH, h = b % HH;
    const int c = blockIdx.x * 128 + threadIdx.x;

    const float* Sp = S + (long long)b * BSTR;
    const float* Vp = V + (long long)b * BSTR;

    float mx = -INFINITY, sum = 0.f;
    for (int s = 0; s < SS; s++) {
        float v  = Sp[(long long)s * SS + c];
        float m2 = fmaxf(mx, v);
        sum = sum * __expf(mx - m2) + __expf(v - m2);
        mx  = m2;
    }
    const float inv = 1.f / sum;

    __half* Yhp = Yh + (long long)n * SS * DD + (long long)h * HD_ + c;
    for (int s = 0; s < SS; s++) {
        float a = __expf(Sp[(long long)s * SS + c] - mx) * inv;
        float y = a * Vp[(long long)s * SS + c];
        Yhp[(long long)s * DD] = __float2half_rn(y);
    }
}

// ---------------------------------------------------------------------------
extern "C" void kernel_launch(void* const* d_in, const int* in_sizes, int n_in,
                              void* d_out, int out_size)
{
    const float* query = (const float*)d_in[0];
    const float* key   = (const float*)d_in[1];
    const float* value = (const float*)d_in[2];
    const float* Wq    = (const float*)d_in[3];
    const float* bq    = (const float*)d_in[4];
    const float* Wk    = (const float*)d_in[5];
    const float* bk    = (const float*)d_in[6];
    const float* Wv    = (const float*)d_in[7];
    const float* bv    = (const float*)d_in[8];
    const float* Wo    = (const float*)d_in[9];
    const float* bo    = (const float*)d_in[10];
    float* out = (float*)d_out;

    float *v, *s;
    __nv_bfloat16 *qa_h,*qa_l,*ka_h,*ka_l,*wq_h,*wq_l,*wk_h,*wk_l,*q_h,*q_l,*k_h,*k_l;
    __half *va,*wv,*wo,*y_h;
    cudaGetSymbolAddress((void**)&v, g_v);     cudaGetSymbolAddress((void**)&s, g_s);
    cudaGetSymbolAddress((void**)&qa_h, g_qa_h); cudaGetSymbolAddress((void**)&qa_l, g_qa_l);
    cudaGetSymbolAddress((void**)&ka_h, g_ka_h); cudaGetSymbolAddress((void**)&ka_l, g_ka_l);
    cudaGetSymbolAddress((void**)&wq_h, g_wq_h); cudaGetSymbolAddress((void**)&wq_l, g_wq_l);
    cudaGetSymbolAddress((void**)&wk_h, g_wk_h); cudaGetSymbolAddress((void**)&wk_l, g_wk_l);
    cudaGetSymbolAddress((void**)&q_h, g_q_h);   cudaGetSymbolAddress((void**)&q_l, g_q_l);
    cudaGetSymbolAddress((void**)&k_h, g_k_h);   cudaGetSymbolAddress((void**)&k_l, g_k_l);
    cudaGetSymbolAddress((void**)&va, g_va);     cudaGetSymbolAddress((void**)&wv, g_wv);
    cudaGetSymbolAddress((void**)&wo, g_wo);
    cudaGetSymbolAddress((void**)&y_h, g_y_h);

    const int SM_W   = 2 * 98304;   // wide 3-pass: 96KB x2 = 192KB, 1 CTA/SM
    const int SM_110 = 3 * 32768;   // 1-pass fp16: 32KB x3 = 96KB, 2 CTA/SM
    cudaFuncSetAttribute((const void*)gemm3_wide,
                         cudaFuncAttributeMaxDynamicSharedMemorySize, SM_W);
    cudaFuncSetAttribute((const void*)gemm1_f16,
                         cudaFuncAttributeMaxDynamicSharedMemorySize, SM_110);

    const int n4 = NELT / 4;
    const int sg = (n4 + 255) / 256;
    const dim3 gp(DD / 256, MT / 128, 1);       // 16 x 32, wide projections
    const dim3 gs(SS / 256, SS / 128, NB * HH); // 2 x 4 x 64, scores (wide)
    const dim3 gf(DD / 128, MT / 128, 1);       // 32 x 32, fp16 full
    const dim3 goh(DD / 128, 16, 1);            // gemmO half: 32x16

    cudaStream_t s1 = g_sx.s1;

    // ---- fork side stream (R14 schedule, unchanged) ----------------------
    cudaEventRecord(g_sx.ef, 0);
    cudaStreamWaitEvent(s1, g_sx.ef, 0);

    // Side stream: K splits -> ek; V splits -> gemmV -> ev; Wo split -> ewo
    split2_bf16<<<sg, 256, 0, s1>>>((const float4*)key, (uint2*)ka_h, (uint2*)ka_l, n4);
    split2_bf16<<<sg, 256, 0, s1>>>((const float4*)Wk,  (uint2*)wk_h, (uint2*)wk_l, n4);
    cudaEventRecord(g_sx.ek, s1);
    split1_f16 <<<sg, 256, 0, s1>>>((const float4*)value, (uint2*)va, n4);
    split1_f16 <<<sg, 256, 0, s1>>>((const float4*)Wv,    (uint2*)wv, n4);
    gemm1_f16<<<gf, 256, SM_110, s1>>>(
        (const uint16_t*)va, (const uint16_t*)wv, v, bv, DD, DD);
    cudaEventRecord(g_sx.ev, s1);
    split1_f16 <<<sg, 256, 0, s1>>>((const float4*)Wo, (uint2*)wo, n4);
    cudaEventRecord(g_sx.ewo, s1);

    // Main stream: Q splits -> gemmQ -> gemmK -> scores
    split2_bf16<<<sg, 256>>>((const float4*)query, (uint2*)qa_h, (uint2*)qa_l, n4);
    split2_bf16<<<sg, 256>>>((const float4*)Wq,    (uint2*)wq_h, (uint2*)wq_l, n4);
    gemm3_wide<<<gp, 256, SM_W>>>(
        (const uint16_t*)qa_h, (const uint16_t*)qa_l,
        (const uint16_t*)wq_h, (const uint16_t*)wq_l,
        nullptr, q_h, q_l, bq, DD, DD, 0, 0, 0, 1.f);
    cudaStreamWaitEvent(0, g_sx.ek, 0);
    gemm3_wide<<<gp, 256, SM_W>>>(
        (const uint16_t*)ka_h, (const uint16_t*)ka_l,
        (const uint16_t*)wk_h, (const uint16_t*)wk_l,
        nullptr, k_h, k_l, bk, DD, DD, 0, 0, 0, 1.f);
    gemm3_wide<<<gs, 256, SM_W>>>(
        (const uint16_t*)q_h, (const uint16_t*)q_l,
        (const uint16_t*)k_h, (const uint16_t*)k_l,
        s, nullptr, nullptr, nullptr, SS, SS, BSTR, BSTR, BSTR,
        0.04419417382415922f);
    cudaEventRecord(g_sx.esc, 0);

    // ---- tail halves (R14, unchanged) ------------------------------------
    cudaStreamWaitEvent(0, g_sx.ev, 0);
    softmax_mul_scatter<<<dim3(4, 32), 128>>>(s, v, y_h, 0);
    cudaStreamWaitEvent(0, g_sx.ewo, 0);
    gemm1_f16<<<goh, 256, SM_110>>>(
        (const uint16_t*)y_h, (const uint16_t*)wo, out, bo, DD, DD);
    cudaStreamWaitEvent(s1, g_sx.esc, 0);
    softmax_mul_scatter<<<dim3(4, 32), 128, 0, s1>>>(s, v, y_h, 32);
    gemm1_f16<<<goh, 256, SM_110, s1>>>(
        (const uint16_t*)(y_h + (long long)2048 * DD), (const uint16_t*)wo,
        out + (long long)2048 * DD, bo, DD, DD);
    cudaEventRecord(g_sx.eoB, s1);
    cudaStreamWaitEvent(0, g_sx.eoB, 0);
}